// round 11
// baseline (speedup 1.0000x reference)
#include <cuda_runtime.h>

// FD_discretizer: warp-strip marching stencil, zero shared memory, slim window.
// Each warp: 32-column strip (30 outputs), marches H=16 rows in y.
// Carries only {eu,ev,ep,eou,eov,dxx,dxy,dex,dey,rJ} per window row (30 regs);
// contravariant/diffusion/pressure quantities re-derived at use (cheap FMA).
// Identities: obm == ebm[interior]; interior ext == raw uvp.

#define NXg 1024
#define NYg 1024
#define EX  1026
#define EY  1026
#define NN  (NXg*NYg)

#define PRESS_E (513*EX + 513)

#define H       16
#define NSTRIP  35                // ceil(1024/30)
#define NCHUNK  64                // 1024/H
#define NWARP   (NSTRIP*NCHUNK)   // 2240
#define BLK     64
#define GRID    (NWARP*32/BLK)    // 1120

__device__ __forceinline__ int clampi(int x, int lo, int hi) {
    return x < lo ? lo : (x > hi ? hi : x);
}
__device__ __forceinline__ int eidx(int je, int ie) {
    return clampi(je - 1, 0, NYg - 1) * NXg + clampi(ie - 1, 0, NXg - 1);
}

struct Row10 {
    float eu, ev, ep, eou, eov;      // BC-enforced field values
    float dxx, dxy, dex, dey, rJ;    // raw metrics + 1/Jm
};

__device__ __forceinline__ void dummy_uv(const float* __restrict__ uvp,
                                         const float* __restrict__ ny,
                                         int m, float& du, float& dv) {
    int io = m % NXg;
    int jo = m / NXg;
    bool bc = (io == 0) || (io != NXg - 1 && (jo == 0 || jo == NYg - 1));
    if (bc) { du = ny[3*m]; dv = ny[3*m+1]; }
    else    { du = uvp[3*m]; dv = uvp[3*m+1]; }
}
__device__ __forceinline__ float dummy_p(const float* __restrict__ uvp, int m) {
    int io = m % NXg;
    return (io == NXg - 1) ? 0.0f : uvp[3*m+2];
}

__device__ __forceinline__ Row10 load_row(
    const float* __restrict__ ouv, const float* __restrict__ ouv_old,
    const float* __restrict__ ny,  const float* __restrict__ ebm,
    int je, int ie)
{
    Row10 d;
    bool jin = (je >= 1) & (je <= EY - 2);
    if (ie == 0 && jin) {                       // left ghost: INFLOW -> pmask
        int m1 = eidx(je, 1), m2 = eidx(je, 2);
        float du, dv; dummy_uv(ouv, ny, m1, du, dv);
        d.eu = 2.0f*du - ouv[3*m2];
        d.ev = 2.0f*dv - ouv[3*m2+1];
        d.ep = ouv[3*m2+2];
        float duo, dvo; dummy_uv(ouv_old, ny, m1, duo, dvo);
        d.eou = 2.0f*duo - ouv_old[3*m2];
        d.eov = 2.0f*dvo - ouv_old[3*m2+1];
    } else if (ie == EX - 1 && jin) {           // right ghost: OUTFLOW -> uvmask
        int m1 = eidx(je, EX - 2), m2 = eidx(je, EX - 3);
        float dp = dummy_p(ouv, m1);
        d.eu = ouv[3*m2];
        d.ev = ouv[3*m2+1];
        d.ep = 2.0f*dp - ouv[3*m2+2];
        d.eou = ouv_old[3*m2];
        d.eov = ouv_old[3*m2+1];
    } else if (je == 0 && ie >= 1 && ie <= EX - 2) {   // bottom ghost: WALL
        int m1 = eidx(1, ie), m2 = eidx(2, ie);
        float du, dv; dummy_uv(ouv, ny, m1, du, dv);
        d.eu = 2.0f*du - ouv[3*m2];
        d.ev = 2.0f*dv - ouv[3*m2+1];
        d.ep = ouv[3*m2+2];
        float duo, dvo; dummy_uv(ouv_old, ny, m1, duo, dvo);
        d.eou = 2.0f*duo - ouv_old[3*m2];
        d.eov = 2.0f*dvo - ouv_old[3*m2+1];
    } else if (je == EY - 1 && ie >= 1 && ie <= EX - 2) {  // top ghost: WALL
        int m1 = eidx(EY - 2, ie), m2 = eidx(EY - 3, ie);
        float du, dv; dummy_uv(ouv, ny, m1, du, dv);
        d.eu = 2.0f*du - ouv[3*m2];
        d.ev = 2.0f*dv - ouv[3*m2+1];
        d.ep = ouv[3*m2+2];
        float duo, dvo; dummy_uv(ouv_old, ny, m1, duo, dvo);
        d.eou = 2.0f*duo - ouv_old[3*m2];
        d.eov = 2.0f*dvo - ouv_old[3*m2+1];
    } else {
        int mm = eidx(je, ie);
        d.eu = ouv[3*mm]; d.ev = ouv[3*mm+1]; d.ep = ouv[3*mm+2];
        d.eou = ouv_old[3*mm]; d.eov = ouv_old[3*mm+1];
    }
    int e = je * EX + ie;
    if (e == PRESS_E) d.ep = 0.0f;

    d.dxx = ebm[5*e + 0];
    d.dxy = ebm[5*e + 1];
    d.dex = ebm[5*e + 2];
    d.dey = ebm[5*e + 3];
    d.rJ  = __fdividef(1.0f, ebm[5*e + 4]);
    return d;
}

#define FULLM 0xffffffffu
#define SHL(x) __shfl_up_sync(FULLM, (x), 1)
#define SHR(x) __shfl_down_sync(FULLM, (x), 1)

__device__ __forceinline__ float Vof(const Row10& r)  { return (r.eu*r.dex + r.ev*r.dey) * r.rJ; }
__device__ __forceinline__ float Voof(const Row10& r) { return (r.eou*r.dex + r.eov*r.dey) * r.rJ; }
__device__ __forceinline__ float a22f(const Row10& r) { return (r.dex*r.dex + r.dey*r.dey) * r.rJ; }

__device__ __forceinline__ void stencil_store(
    const Row10& m, const Row10& c, const Row10& p,
    int jo, int io, bool wr,
    float cc, float cn, float co, float ucv, float pcv, float dcv, float rdt,
    float* __restrict__ out)
{
    // center-row derived
    float Uc  = (c.eu*c.dxx + c.ev*c.dxy) * c.rJ;
    float Uoc = (c.eou*c.dxx + c.eov*c.dxy) * c.rJ;
    float a11 = (c.dxx*c.dxx + c.dxy*c.dxy) * c.rJ;
    float pqc = c.ep * c.rJ;
    float pxx = pqc * c.dxx;
    float pxy = pqc * c.dxy;
    // row derived (m,c,p)
    float Vm = Vof(m),  Vc = Vof(c),  Vp = Vof(p);
    float Vom = Voof(m), Voc = Voof(c), Vop = Voof(p);
    float a22m = a22f(m), a22c = a22f(c), a22p = a22f(p);
    float pexm = m.ep * m.rJ * m.dex, pexp = p.ep * p.rJ * p.dex;
    float peym = m.ep * m.rJ * m.dey, peyp = p.ep * p.rJ * p.dey;

    // shuffles (x-neighbors)
    float UL = SHL(Uc),    UR = SHR(Uc);
    float UoL = SHL(Uoc),  UoR = SHR(Uoc);
    float a11L = SHL(a11), a11R = SHR(a11);
    float pxxL = SHL(pxx), pxxR = SHR(pxx);
    float pxyL = SHL(pxy), pxyR = SHR(pxy);
    float euL = SHL(c.eu), euR = SHR(c.eu);
    float evL = SHL(c.ev), evR = SHR(c.ev);
    float epL = SHL(c.ep), epR = SHR(c.ep);
    float ouL = SHL(c.eou), ouR = SHR(c.eou);
    float ovL = SHL(c.eov), ovR = SHR(c.eov);
    float eumL = SHL(m.eu), eumR = SHR(m.eu);
    float eupL = SHL(p.eu), eupR = SHR(p.eu);
    float evmL = SHL(m.ev), evmR = SHR(m.ev);
    float evpL = SHL(p.ev), evpR = SHR(p.ev);
    float epmL = SHL(m.ep), epmR = SHR(m.ep);
    float eppL = SHL(p.ep), eppR = SHR(p.ep);

    // continuity
    float loss = 0.5f * ((UR - UL) + (Vp - Vm)) * cc;

    // convection (new)
    float cnu = 0.25f * ((c.eu + euR) * (Uc + UR) - (euL + c.eu) * (UL + Uc))
              + 0.25f * ((c.eu + p.eu) * (Vc + Vp) - (m.eu + c.eu) * (Vm + Vc));
    float cnv = 0.25f * ((c.ev + evR) * (Uc + UR) - (evL + c.ev) * (UL + Uc))
              + 0.25f * ((c.ev + p.ev) * (Vc + Vp) - (m.ev + c.ev) * (Vm + Vc));

    // convection (old)
    float cou = 0.25f * ((c.eou + ouR) * (Uoc + UoR) - (ouL + c.eou) * (UoL + Uoc))
              + 0.25f * ((c.eou + p.eou) * (Voc + Vop) - (m.eou + c.eou) * (Vom + Voc));
    float cov = 0.25f * ((c.eov + ovR) * (Uoc + UoR) - (ovL + c.eov) * (UoL + Uoc))
              + 0.25f * ((c.eov + p.eov) * (Voc + Vop) - (m.eov + c.eov) * (Vom + Voc));

    // diffusion (new)
    float difu = 0.5f * ((a11 + a11R) * (euR - c.eu) - (a11L + a11) * (c.eu - euL))
               + 0.5f * ((a22c + a22p) * (p.eu - c.eu) - (a22m + a22c) * (c.eu - m.eu));
    float difv = 0.5f * ((a11 + a11R) * (evR - c.ev) - (a11L + a11) * (c.ev - evL))
               + 0.5f * ((a22c + a22p) * (p.ev - c.ev) - (a22m + a22c) * (c.ev - m.ev));

    // pressure gradient
    float gPx = 0.5f * (pxxR - pxxL) + 0.5f * (pexp - pexm);
    float gPy = 0.5f * (peyp - peym) + 0.5f * (pxyR - pxyL);

    // unsteady (J_o == Jm at interior)
    float inv = c.rJ * rdt;
    float momu = ucv * (c.eu - c.eou) * inv + cn * cnu + co * cou + pcv * gPx - dcv * difu;
    float momv = ucv * (c.ev - c.eov) * inv + cn * cnv + co * cov + pcv * gPy - dcv * difv;

    // uvp_to_vis: (1-2-1)^2 / 16 binomial
    const float swt = 1.0f / 16.0f;
    float visu = swt * (4.0f*c.eu + 2.0f*(euL + euR + m.eu + p.eu) + (eumL + eumR + eupL + eupR));
    float visv = swt * (4.0f*c.ev + 2.0f*(evL + evR + m.ev + p.ev) + (evmL + evmR + evpL + evpR));
    float visp = swt * (4.0f*c.ep + 2.0f*(epL + epR + m.ep + p.ep) + (epmL + epmR + eppL + eppR));

    if (wr) {
        int o = jo * NXg + io;
        out[o]          = loss;
        out[NN + o]     = momu;
        out[2*NN + o]   = momv;
        out[3*NN + 3*o]     = visu;
        out[3*NN + 3*o + 1] = visv;
        out[3*NN + 3*o + 2] = visp;
    }
}

__global__ void __launch_bounds__(BLK, 10)
fused_kernel(const float* __restrict__ ouv,
             const float* __restrict__ ouv_old,
             const float* __restrict__ ny,
             const float* __restrict__ ebm,
             const float* __restrict__ dtg,
             const float* __restrict__ theta,
             const float* __restrict__ relp,
             float* __restrict__ out)
{
    const int gtid = blockIdx.x * BLK + threadIdx.x;
    const int wid  = gtid >> 5;
    const int lane = gtid & 31;

    const int strip = wid % NSTRIP;
    const int chunk = wid / NSTRIP;

    int ie = strip * 30 + lane;
    if (ie > EX - 1) ie = EX - 1;
    const int io  = ie - 1;
    const int jo0 = chunk * H;

    const float rdt   = __fdividef(1.0f, __ldg(dtg));
    const float ucv   = __ldg(theta + 0);
    const float cc    = __ldg(theta + 1);
    const float convc = __ldg(theta + 2);
    const float pcv   = __ldg(theta + 3);
    const float dcv   = __ldg(theta + 4);
    const float relax = __ldg(relp);
    const float cn = convc * (1.0f - relax);
    const float co = convc * relax;

    const bool wr_lane = (lane >= 1) && (lane <= 30) && (io < NXg);

    Row10 w0 = load_row(ouv, ouv_old, ny, ebm, jo0,     ie);
    Row10 w1 = load_row(ouv, ouv_old, ny, ebm, jo0 + 1, ie);
    Row10 w2;

    // H=16 rows: 5 x (3 rows) + 1 epilogue row. ext rows jo0+2 .. jo0+17 <= 1025.
    for (int jb = 0; jb < 15; jb += 3) {
        w2 = load_row(ouv, ouv_old, ny, ebm, jo0 + jb + 2, ie);
        stencil_store(w0, w1, w2, jo0 + jb,     io, wr_lane, cc, cn, co, ucv, pcv, dcv, rdt, out);
        w0 = load_row(ouv, ouv_old, ny, ebm, jo0 + jb + 3, ie);
        stencil_store(w1, w2, w0, jo0 + jb + 1, io, wr_lane, cc, cn, co, ucv, pcv, dcv, rdt, out);
        w1 = load_row(ouv, ouv_old, ny, ebm, jo0 + jb + 4, ie);
        stencil_store(w2, w0, w1, jo0 + jb + 2, io, wr_lane, cc, cn, co, ucv, pcv, dcv, rdt, out);
    }
    // epilogue: output row jo0+15 (ext rows jo0+15, jo0+16, jo0+17)
    w2 = load_row(ouv, ouv_old, ny, ebm, jo0 + 17, ie);
    stencil_store(w0, w1, w2, jo0 + 15, io, wr_lane, cc, cn, co, ucv, pcv, dcv, rdt, out);
}

extern "C" void kernel_launch(void* const* d_in, const int* in_sizes, int n_in,
                              void* d_out, int out_size) {
    const float* ouv     = (const float*)d_in[0];
    const float* ouv_old = (const float*)d_in[1];
    const float* ny      = (const float*)d_in[2];
    // d_in[3] (obm) unused: obm == ebm[interior]
    const float* ebm     = (const float*)d_in[4];
    const float* dtg     = (const float*)d_in[5];
    const float* theta   = (const float*)d_in[6];
    const float* relp    = (const float*)d_in[7];
    float* out = (float*)d_out;

    fused_kernel<<<GRID, BLK>>>(ouv, ouv_old, ny, ebm, dtg, theta, relp, out);
}

// round 12
// speedup vs baseline: 1.1385x; 1.1385x over previous
#include <cuda_runtime.h>

// FD_discretizer: warp-strip marching stencil, zero shared memory, slim window.
// Each warp: 32-column strip (30 outputs), marches H=8 rows in y (128 chunks
// -> 4480 warps, ~30/SM available; previously H=16 gave only 15/SM).
// Carries only {eu,ev,ep,eou,eov,dxx,dxy,dex,dey,rJ} per window row;
// derived quantities recomputed at use. obm == ebm[interior]; interior ext == raw uvp.

#define NXg 1024
#define NYg 1024
#define EX  1026
#define EY  1026
#define NN  (NXg*NYg)

#define PRESS_E (513*EX + 513)

#define H       8
#define NSTRIP  35                // ceil(1024/30)
#define NCHUNK  (NYg/H)           // 128
#define NWARP   (NSTRIP*NCHUNK)   // 4480
#define BLK     64
#define GRID    (NWARP*32/BLK)    // 2240

__device__ __forceinline__ int clampi(int x, int lo, int hi) {
    return x < lo ? lo : (x > hi ? hi : x);
}
__device__ __forceinline__ int eidx(int je, int ie) {
    return clampi(je - 1, 0, NYg - 1) * NXg + clampi(ie - 1, 0, NXg - 1);
}

struct Row10 {
    float eu, ev, ep, eou, eov;      // BC-enforced field values
    float dxx, dxy, dex, dey, rJ;    // raw metrics + 1/Jm
};

__device__ __forceinline__ void dummy_uv(const float* __restrict__ uvp,
                                         const float* __restrict__ ny,
                                         int m, float& du, float& dv) {
    int io = m % NXg;
    int jo = m / NXg;
    bool bc = (io == 0) || (io != NXg - 1 && (jo == 0 || jo == NYg - 1));
    if (bc) { du = ny[3*m]; dv = ny[3*m+1]; }
    else    { du = uvp[3*m]; dv = uvp[3*m+1]; }
}
__device__ __forceinline__ float dummy_p(const float* __restrict__ uvp, int m) {
    int io = m % NXg;
    return (io == NXg - 1) ? 0.0f : uvp[3*m+2];
}

__device__ __forceinline__ Row10 load_row(
    const float* __restrict__ ouv, const float* __restrict__ ouv_old,
    const float* __restrict__ ny,  const float* __restrict__ ebm,
    int je, int ie)
{
    Row10 d;
    bool jin = (je >= 1) & (je <= EY - 2);
    if (ie == 0 && jin) {                       // left ghost: INFLOW -> pmask
        int m1 = eidx(je, 1), m2 = eidx(je, 2);
        float du, dv; dummy_uv(ouv, ny, m1, du, dv);
        d.eu = 2.0f*du - ouv[3*m2];
        d.ev = 2.0f*dv - ouv[3*m2+1];
        d.ep = ouv[3*m2+2];
        float duo, dvo; dummy_uv(ouv_old, ny, m1, duo, dvo);
        d.eou = 2.0f*duo - ouv_old[3*m2];
        d.eov = 2.0f*dvo - ouv_old[3*m2+1];
    } else if (ie == EX - 1 && jin) {           // right ghost: OUTFLOW -> uvmask
        int m1 = eidx(je, EX - 2), m2 = eidx(je, EX - 3);
        float dp = dummy_p(ouv, m1);
        d.eu = ouv[3*m2];
        d.ev = ouv[3*m2+1];
        d.ep = 2.0f*dp - ouv[3*m2+2];
        d.eou = ouv_old[3*m2];
        d.eov = ouv_old[3*m2+1];
    } else if (je == 0 && ie >= 1 && ie <= EX - 2) {   // bottom ghost: WALL
        int m1 = eidx(1, ie), m2 = eidx(2, ie);
        float du, dv; dummy_uv(ouv, ny, m1, du, dv);
        d.eu = 2.0f*du - ouv[3*m2];
        d.ev = 2.0f*dv - ouv[3*m2+1];
        d.ep = ouv[3*m2+2];
        float duo, dvo; dummy_uv(ouv_old, ny, m1, duo, dvo);
        d.eou = 2.0f*duo - ouv_old[3*m2];
        d.eov = 2.0f*dvo - ouv_old[3*m2+1];
    } else if (je == EY - 1 && ie >= 1 && ie <= EX - 2) {  // top ghost: WALL
        int m1 = eidx(EY - 2, ie), m2 = eidx(EY - 3, ie);
        float du, dv; dummy_uv(ouv, ny, m1, du, dv);
        d.eu = 2.0f*du - ouv[3*m2];
        d.ev = 2.0f*dv - ouv[3*m2+1];
        d.ep = ouv[3*m2+2];
        float duo, dvo; dummy_uv(ouv_old, ny, m1, duo, dvo);
        d.eou = 2.0f*duo - ouv_old[3*m2];
        d.eov = 2.0f*dvo - ouv_old[3*m2+1];
    } else {
        int mm = eidx(je, ie);
        d.eu = ouv[3*mm]; d.ev = ouv[3*mm+1]; d.ep = ouv[3*mm+2];
        d.eou = ouv_old[3*mm]; d.eov = ouv_old[3*mm+1];
    }
    int e = je * EX + ie;
    if (e == PRESS_E) d.ep = 0.0f;

    d.dxx = ebm[5*e + 0];
    d.dxy = ebm[5*e + 1];
    d.dex = ebm[5*e + 2];
    d.dey = ebm[5*e + 3];
    d.rJ  = __fdividef(1.0f, ebm[5*e + 4]);
    return d;
}

#define FULLM 0xffffffffu
#define SHL(x) __shfl_up_sync(FULLM, (x), 1)
#define SHR(x) __shfl_down_sync(FULLM, (x), 1)

__device__ __forceinline__ float Vof(const Row10& r)  { return (r.eu*r.dex + r.ev*r.dey) * r.rJ; }
__device__ __forceinline__ float Voof(const Row10& r) { return (r.eou*r.dex + r.eov*r.dey) * r.rJ; }
__device__ __forceinline__ float a22f(const Row10& r) { return (r.dex*r.dex + r.dey*r.dey) * r.rJ; }

__device__ __forceinline__ void stencil_store(
    const Row10& m, const Row10& c, const Row10& p,
    int jo, int io, bool wr,
    float cc, float cn, float co, float ucv, float pcv, float dcv, float rdt,
    float* __restrict__ out)
{
    // center-row derived
    float Uc  = (c.eu*c.dxx + c.ev*c.dxy) * c.rJ;
    float Uoc = (c.eou*c.dxx + c.eov*c.dxy) * c.rJ;
    float a11 = (c.dxx*c.dxx + c.dxy*c.dxy) * c.rJ;
    float pqc = c.ep * c.rJ;
    float pxx = pqc * c.dxx;
    float pxy = pqc * c.dxy;
    // row derived (m,c,p)
    float Vm = Vof(m),  Vc = Vof(c),  Vp = Vof(p);
    float Vom = Voof(m), Voc = Voof(c), Vop = Voof(p);
    float a22m = a22f(m), a22c = a22f(c), a22p = a22f(p);
    float pexm = m.ep * m.rJ * m.dex, pexp = p.ep * p.rJ * p.dex;
    float peym = m.ep * m.rJ * m.dey, peyp = p.ep * p.rJ * p.dey;

    // shuffles (x-neighbors)
    float UL = SHL(Uc),    UR = SHR(Uc);
    float UoL = SHL(Uoc),  UoR = SHR(Uoc);
    float a11L = SHL(a11), a11R = SHR(a11);
    float pxxL = SHL(pxx), pxxR = SHR(pxx);
    float pxyL = SHL(pxy), pxyR = SHR(pxy);
    float euL = SHL(c.eu), euR = SHR(c.eu);
    float evL = SHL(c.ev), evR = SHR(c.ev);
    float epL = SHL(c.ep), epR = SHR(c.ep);
    float ouL = SHL(c.eou), ouR = SHR(c.eou);
    float ovL = SHL(c.eov), ovR = SHR(c.eov);
    float eumL = SHL(m.eu), eumR = SHR(m.eu);
    float eupL = SHL(p.eu), eupR = SHR(p.eu);
    float evmL = SHL(m.ev), evmR = SHR(m.ev);
    float evpL = SHL(p.ev), evpR = SHR(p.ev);
    float epmL = SHL(m.ep), epmR = SHR(m.ep);
    float eppL = SHL(p.ep), eppR = SHR(p.ep);

    // continuity
    float loss = 0.5f * ((UR - UL) + (Vp - Vm)) * cc;

    // convection (new)
    float cnu = 0.25f * ((c.eu + euR) * (Uc + UR) - (euL + c.eu) * (UL + Uc))
              + 0.25f * ((c.eu + p.eu) * (Vc + Vp) - (m.eu + c.eu) * (Vm + Vc));
    float cnv = 0.25f * ((c.ev + evR) * (Uc + UR) - (evL + c.ev) * (UL + Uc))
              + 0.25f * ((c.ev + p.ev) * (Vc + Vp) - (m.ev + c.ev) * (Vm + Vc));

    // convection (old)
    float cou = 0.25f * ((c.eou + ouR) * (Uoc + UoR) - (ouL + c.eou) * (UoL + Uoc))
              + 0.25f * ((c.eou + p.eou) * (Voc + Vop) - (m.eou + c.eou) * (Vom + Voc));
    float cov = 0.25f * ((c.eov + ovR) * (Uoc + UoR) - (ovL + c.eov) * (UoL + Uoc))
              + 0.25f * ((c.eov + p.eov) * (Voc + Vop) - (m.eov + c.eov) * (Vom + Voc));

    // diffusion (new)
    float difu = 0.5f * ((a11 + a11R) * (euR - c.eu) - (a11L + a11) * (c.eu - euL))
               + 0.5f * ((a22c + a22p) * (p.eu - c.eu) - (a22m + a22c) * (c.eu - m.eu));
    float difv = 0.5f * ((a11 + a11R) * (evR - c.ev) - (a11L + a11) * (c.ev - evL))
               + 0.5f * ((a22c + a22p) * (p.ev - c.ev) - (a22m + a22c) * (c.ev - m.ev));

    // pressure gradient
    float gPx = 0.5f * (pxxR - pxxL) + 0.5f * (pexp - pexm);
    float gPy = 0.5f * (peyp - peym) + 0.5f * (pxyR - pxyL);

    // unsteady (J_o == Jm at interior)
    float inv = c.rJ * rdt;
    float momu = ucv * (c.eu - c.eou) * inv + cn * cnu + co * cou + pcv * gPx - dcv * difu;
    float momv = ucv * (c.ev - c.eov) * inv + cn * cnv + co * cov + pcv * gPy - dcv * difv;

    // uvp_to_vis: (1-2-1)^2 / 16 binomial
    const float swt = 1.0f / 16.0f;
    float visu = swt * (4.0f*c.eu + 2.0f*(euL + euR + m.eu + p.eu) + (eumL + eumR + eupL + eupR));
    float visv = swt * (4.0f*c.ev + 2.0f*(evL + evR + m.ev + p.ev) + (evmL + evmR + evpL + evpR));
    float visp = swt * (4.0f*c.ep + 2.0f*(epL + epR + m.ep + p.ep) + (epmL + epmR + eppL + eppR));

    if (wr) {
        int o = jo * NXg + io;
        out[o]          = loss;
        out[NN + o]     = momu;
        out[2*NN + o]   = momv;
        out[3*NN + 3*o]     = visu;
        out[3*NN + 3*o + 1] = visv;
        out[3*NN + 3*o + 2] = visp;
    }
}

__global__ void __launch_bounds__(BLK, 12)
fused_kernel(const float* __restrict__ ouv,
             const float* __restrict__ ouv_old,
             const float* __restrict__ ny,
             const float* __restrict__ ebm,
             const float* __restrict__ dtg,
             const float* __restrict__ theta,
             const float* __restrict__ relp,
             float* __restrict__ out)
{
    const int gtid = blockIdx.x * BLK + threadIdx.x;
    const int wid  = gtid >> 5;
    const int lane = gtid & 31;

    const int strip = wid % NSTRIP;
    const int chunk = wid / NSTRIP;

    int ie = strip * 30 + lane;
    if (ie > EX - 1) ie = EX - 1;
    const int io  = ie - 1;
    const int jo0 = chunk * H;

    const float rdt   = __fdividef(1.0f, __ldg(dtg));
    const float ucv   = __ldg(theta + 0);
    const float cc    = __ldg(theta + 1);
    const float convc = __ldg(theta + 2);
    const float pcv   = __ldg(theta + 3);
    const float dcv   = __ldg(theta + 4);
    const float relax = __ldg(relp);
    const float cn = convc * (1.0f - relax);
    const float co = convc * relax;

    const bool wr_lane = (lane >= 1) && (lane <= 30) && (io < NXg);

    // Rolling 3-row window; compile-time modular indices (full unroll => renaming).
    Row10 w[3];
    w[0] = load_row(ouv, ouv_old, ny, ebm, jo0,     ie);
    w[1] = load_row(ouv, ouv_old, ny, ebm, jo0 + 1, ie);

    #pragma unroll
    for (int t = 0; t < H; t++) {
        w[(t + 2) % 3] = load_row(ouv, ouv_old, ny, ebm, jo0 + t + 2, ie);
        stencil_store(w[t % 3], w[(t + 1) % 3], w[(t + 2) % 3],
                      jo0 + t, io, wr_lane,
                      cc, cn, co, ucv, pcv, dcv, rdt, out);
    }
}

extern "C" void kernel_launch(void* const* d_in, const int* in_sizes, int n_in,
                              void* d_out, int out_size) {
    const float* ouv     = (const float*)d_in[0];
    const float* ouv_old = (const float*)d_in[1];
    const float* ny      = (const float*)d_in[2];
    // d_in[3] (obm) unused: obm == ebm[interior]
    const float* ebm     = (const float*)d_in[4];
    const float* dtg     = (const float*)d_in[5];
    const float* theta   = (const float*)d_in[6];
    const float* relp    = (const float*)d_in[7];
    float* out = (float*)d_out;

    fused_kernel<<<GRID, BLK>>>(ouv, ouv_old, ny, ebm, dtg, theta, relp, out);
}